// round 14
// baseline (speedup 1.0000x reference)
#include <cuda_runtime.h>

// AggregateJoint: per-row block-diagonal MLP 64 -> (16x16) -> (16x3)
// with leaky_relu + folded batchnorm. Shapes fixed: x (256, 64, 512).
//
// Design (R14): single PERFECT wave (grid 592 = 148 SMs x 4 CTAs), part-
// resident CTAs (16 parts x 37 slices), <=64 regs -> 4 CTA/SM -> 8 warps
// per SMSP (2.3x R13). Per-thread state shrunk to 2 f-columns; weights stay
// in smem and are re-LDS'd per iteration (broadcast, rt=2) — trading ~20%
// more instructions for 2.3x more eligible warps. Threads grid-stride over
// their part's 65536 column-pairs (~7 iters). Packed fp32 math
// (fma.rn.f32x2), pairs along hidden dim; BN folded; leaky packed.

#define B_DIM 256
#define N_DIM 64
#define F_DIM 512
#define P_DIM 16
#define IN_DIM 4
#define H_DIM 16
#define O_DIM 3
#define SLICES 37
#define GRID (P_DIM * SLICES)          // 592 = 148*4
#define STRIDE (SLICES * 256)          // 9472 threads per part
#define UNITS 65536                    // col-pairs per part (256*512/2)

typedef unsigned long long u64;

__device__ __forceinline__ u64 f2fma(u64 a, u64 b, u64 c) {
    u64 d;
    asm("fma.rn.f32x2 %0, %1, %2, %3;" : "=l"(d) : "l"(a), "l"(b), "l"(c));
    return d;
}
__device__ __forceinline__ u64 f2mul(u64 a, u64 b) {
    u64 d;
    asm("mul.rn.f32x2 %0, %1, %2;" : "=l"(d) : "l"(a), "l"(b));
    return d;
}
__device__ __forceinline__ u64 packf2(float lo, float hi) {
    u64 r;
    asm("mov.b64 %0, {%1, %2};" : "=l"(r) : "f"(lo), "f"(hi));
    return r;
}
__device__ __forceinline__ void unpackf2(u64 v, float& lo, float& hi) {
    asm("mov.b64 {%0, %1}, %2;" : "=f"(lo), "=f"(hi) : "l"(v));
}

__global__ __launch_bounds__(256, 4)
void aggregate_joint_kernel(
    const float* __restrict__ x, const int* __restrict__ parts,
    const float* __restrict__ W1, const float* __restrict__ b1,
    const float* __restrict__ W2, const float* __restrict__ b2,
    const float* __restrict__ gamma, const float* __restrict__ beta,
    const float* __restrict__ mean, const float* __restrict__ var,
    float* __restrict__ out)
{
    // this CTA's single part
    __shared__ __align__(16) float sW1[IN_DIM * H_DIM];   // 64
    __shared__ __align__(16) float sW2T[O_DIM * H_DIM];   // 48
    __shared__ __align__(16) float sB1[H_DIM];            // 16
    __shared__ float sSc[O_DIM];
    __shared__ float sSh[O_DIM];
    __shared__ int   sNi[IN_DIM];

    const int tid   = threadIdx.x;
    const int p     = blockIdx.x & 15;       // part (592 = 37*16)
    const int slice = blockIdx.x >> 4;       // 0..36

    // ---- stage this part's weights (L2-hit), fold BN ----
    if (tid < 64) {
        sW1[tid] = W1[p * (IN_DIM * H_DIM) + tid];
    } else if (tid < 112) {
        int idx = tid - 64;                  // 0..47
        int o = idx >> 4;
        int hh = idx & 15;
        sW2T[idx] = W2[(p * H_DIM + hh) * O_DIM + o];
    } else if (tid < 128) {
        sB1[tid - 112] = b1[p * H_DIM + (tid - 112)];
    } else if (tid < 128 + O_DIM) {
        int o = tid - 128;
        int g = p * O_DIM + o;
        float s = gamma[g] * rsqrtf(var[g] + 1e-5f);
        sSc[o] = s;
        sSh[o] = (b2[g] - mean[g]) * s + beta[g];
    } else if (tid < 128 + O_DIM + IN_DIM) {
        int i = tid - (128 + O_DIM);
        sNi[i] = parts[p * IN_DIM + i];
    }
    __syncthreads();

    // x row offsets for this part's 4 inputs (warp-uniform, hoisted)
    const int n0 = sNi[0] * F_DIM;
    const int n1 = sNi[1] * F_DIM;
    const int n2 = sNi[2] * F_DIM;
    const int n3 = sNi[3] * F_DIM;
    const int obase = p * (O_DIM * F_DIM);   // p*1536

    // leaky(x) = 0.505*x + 0.495*|x|
    const u64 AP = packf2(0.505f, 0.505f);
    const u64 BP = packf2(0.495f, 0.495f);

#pragma unroll 1
    for (int u = slice * 256 + tid; u < UNITS; u += STRIDE) {
        const int col = u << 1;              // even f-column
        const int b   = col >> 9;
        const int f   = col & 511;
        const float* xp = x + b * (N_DIM * F_DIM) + f;
        float* op = out + b * (P_DIM * O_DIM * F_DIM) + obase + f;

        // front-batched independent loads (MLP=4)
        float2 x0 = *(const float2*)(xp + n0);
        float2 x1 = *(const float2*)(xp + n1);
        float2 x2 = *(const float2*)(xp + n2);
        float2 x3 = *(const float2*)(xp + n3);

        // h pairs init from b1
        const ulonglong2* bb = (const ulonglong2*)sB1;
        ulonglong2 t0 = bb[0], t1 = bb[1], t2 = bb[2], t3 = bb[3];
        u64 ha[8] = {t0.x, t0.y, t1.x, t1.y, t2.x, t2.y, t3.x, t3.y};
        u64 hb[8] = {t0.x, t0.y, t1.x, t1.y, t2.x, t2.y, t3.x, t3.y};

        // layer 1: weights broadcast-LDS'd per i, 2 independent chains
#pragma unroll
        for (int i = 0; i < IN_DIM; i++) {
            float2 xi = (i == 0) ? x0 : (i == 1) ? x1 : (i == 2) ? x2 : x3;
            u64 sa = packf2(xi.x, xi.x);
            u64 sb = packf2(xi.y, xi.y);
            const ulonglong2* wr = (const ulonglong2*)&sW1[i * H_DIM];
            ulonglong2 w0 = wr[0], w1 = wr[1], w2r = wr[2], w3 = wr[3];
            ha[0] = f2fma(sa, w0.x, ha[0]);  hb[0] = f2fma(sb, w0.x, hb[0]);
            ha[1] = f2fma(sa, w0.y, ha[1]);  hb[1] = f2fma(sb, w0.y, hb[1]);
            ha[2] = f2fma(sa, w1.x, ha[2]);  hb[2] = f2fma(sb, w1.x, hb[2]);
            ha[3] = f2fma(sa, w1.y, ha[3]);  hb[3] = f2fma(sb, w1.y, hb[3]);
            ha[4] = f2fma(sa, w2r.x, ha[4]); hb[4] = f2fma(sb, w2r.x, hb[4]);
            ha[5] = f2fma(sa, w2r.y, ha[5]); hb[5] = f2fma(sb, w2r.y, hb[5]);
            ha[6] = f2fma(sa, w3.x, ha[6]);  hb[6] = f2fma(sb, w3.x, hb[6]);
            ha[7] = f2fma(sa, w3.y, ha[7]);  hb[7] = f2fma(sb, w3.y, hb[7]);
        }

        // packed leaky relu
#pragma unroll
        for (int j = 0; j < 8; j++) {
            u64 aa = ha[j] & 0x7FFFFFFF7FFFFFFFULL;
            ha[j] = f2fma(aa, BP, f2mul(ha[j], AP));
            u64 ab = hb[j] & 0x7FFFFFFF7FFFFFFFULL;
            hb[j] = f2fma(ab, BP, f2mul(hb[j], AP));
        }

        // layer 2 + BN + leaky + store
#pragma unroll
        for (int o = 0; o < O_DIM; o++) {
            const ulonglong2* wr = (const ulonglong2*)&sW2T[o * H_DIM];
            ulonglong2 a0 = wr[0], a1 = wr[1], a2 = wr[2], a3 = wr[3];
            u64 acca = f2mul(ha[0], a0.x);
            u64 accb = f2mul(hb[0], a0.x);
            acca = f2fma(ha[1], a0.y, acca);  accb = f2fma(hb[1], a0.y, accb);
            acca = f2fma(ha[2], a1.x, acca);  accb = f2fma(hb[2], a1.x, accb);
            acca = f2fma(ha[3], a1.y, acca);  accb = f2fma(hb[3], a1.y, accb);
            acca = f2fma(ha[4], a2.x, acca);  accb = f2fma(hb[4], a2.x, accb);
            acca = f2fma(ha[5], a2.y, acca);  accb = f2fma(hb[5], a2.y, accb);
            acca = f2fma(ha[6], a3.x, acca);  accb = f2fma(hb[6], a3.x, accb);
            acca = f2fma(ha[7], a3.y, acca);  accb = f2fma(hb[7], a3.y, accb);

            float la, hA, lb, hB;
            unpackf2(acca, la, hA);
            unpackf2(accb, lb, hB);
            const float sc = sSc[o];
            const float sh = sSh[o];
            float va = fmaf(la + hA, sc, sh);
            float vb = fmaf(lb + hB, sc, sh);
            va = fmaxf(va, 0.01f * va);
            vb = fmaxf(vb, 0.01f * vb);
            *(float2*)(op + o * F_DIM) = make_float2(va, vb);
        }
    }
}

extern "C" void kernel_launch(void* const* d_in, const int* in_sizes, int n_in,
                              void* d_out, int out_size) {
    const float* x     = (const float*)d_in[0];
    const int*   parts = (const int*)d_in[1];
    const float* W1    = (const float*)d_in[2];
    const float* b1    = (const float*)d_in[3];
    const float* W2    = (const float*)d_in[4];
    const float* b2    = (const float*)d_in[5];
    const float* gamma = (const float*)d_in[6];
    const float* beta  = (const float*)d_in[7];
    const float* mean  = (const float*)d_in[8];
    const float* var   = (const float*)d_in[9];
    float* out = (float*)d_out;

    // 592 CTAs = 148 SMs x 4 — one perfectly balanced wave
    aggregate_joint_kernel<<<GRID, 256>>>(x, parts, W1, b1, W2, b2,
                                          gamma, beta, mean, var, out);
}